// round 2
// baseline (speedup 1.0000x reference)
#include <cuda_runtime.h>
#include <math.h>

#define NN   100000
#define FIN  256
#define FH   50
#define FHP  52        // padded hidden width (13 float4)
#define FOUT 40        // 10 float4
#define EE   3200000
#define ET   (EE + NN) // edges + self loops

// ---------------- scratch (device globals; no allocation) ----------------
__device__ __align__(16) float g_h1[NN * FHP];   // x@W1+b1  (padded)
__device__ __align__(16) float g_a1[NN * FHP];   // aggregated layer1 (padded)
__device__ __align__(16) float g_h2[NN * FOUT];  // relu(a1)@W2+b2
__device__ __align__(16) float g_deg[NN];
__device__ int   g_row[ET];
__device__ int   g_col[ET];
__device__ float g_norm[ET];

// sm_90+ vector reduction: 4 floats per L2 atomic
__device__ __forceinline__ void red_add_v4(float* p, float4 v) {
    asm volatile("red.global.add.v4.f32 [%0], {%1,%2,%3,%4};"
                 :: "l"(p), "f"(v.x), "f"(v.y), "f"(v.z), "f"(v.w)
                 : "memory");
}

// ---------------- zeroing ----------------
__global__ void zero_scratch_kernel() {
    int i = blockIdx.x * blockDim.x + threadIdx.x;
    const float4 z = make_float4(0.f, 0.f, 0.f, 0.f);
    if (i < NN * FHP / 4) reinterpret_cast<float4*>(g_a1)[i] = z;
    if (i < NN / 4)       reinterpret_cast<float4*>(g_deg)[i] = z;
}

__global__ void zero_out_kernel(float4* out) {
    int i = blockIdx.x * blockDim.x + threadIdx.x;
    if (i < NN * FOUT / 4) out[i] = make_float4(0.f, 0.f, 0.f, 0.f);
}

// ---------------- graph prep ----------------
// edge_index: JAX default config has x64 DISABLED, so the "int64" request
// silently becomes int32. Layout [2, E] row-major: rows at ei[0..E),
// cols at ei[E..2E).
__global__ void prep_kernel(const int* __restrict__ ei) {
    int e = blockIdx.x * blockDim.x + threadIdx.x;
    if (e >= ET) return;
    int r, c;
    if (e < EE) {
        r = ei[e];
        c = ei[EE + e];
    } else {
        r = c = e - EE;
    }
    // defensive clamp: if dtype interpretation is wrong this turns a crash
    // into a measurable rel_err signal instead
    if ((unsigned)r >= NN) r = 0;
    if ((unsigned)c >= NN) c = 0;
    g_row[e] = r;
    g_col[e] = c;
    atomicAdd(&g_deg[c], 1.0f);
}

__global__ void norm_kernel() {
    int e = blockIdx.x * blockDim.x + threadIdx.x;
    if (e >= ET) return;
    float dr = g_deg[g_row[e]];
    float dc = g_deg[g_col[e]];
    float a = (dr > 0.f) ? rsqrtf(dr) : 0.f;
    float b = (dc > 0.f) ? rsqrtf(dc) : 0.f;
    g_norm[e] = a * b;
}

// ---------------- GEMM1: h1 = x @ W1 + b1   (M=100000, K=256, Ncols=50) ----------------
// BM=64, BN=64 (padded from 50), BK=16; 256 threads (16x16), 4x4 per thread.
__global__ void gemm1_kernel(const float* __restrict__ x,
                             const float* __restrict__ W,
                             const float* __restrict__ b) {
    __shared__ __align__(16) float Xs[16][68];  // [BK][BM+4]
    __shared__ __align__(16) float Ws[16][64];

    int tid = threadIdx.x;
    int tx = tid & 15;         // col tile
    int ty = tid >> 4;         // row tile
    int rowBase = blockIdx.x * 64;

    float acc[4][4];
#pragma unroll
    for (int i = 0; i < 4; i++)
#pragma unroll
        for (int j = 0; j < 4; j++) acc[i][j] = 0.f;

    for (int k0 = 0; k0 < FIN; k0 += 16) {
        // load X tile (64 rows x 16 k), transposed into Xs[k][row]
        {
            int r = tid >> 2, seg = tid & 3;
            int grow = rowBase + r;
            float4 xv = make_float4(0.f, 0.f, 0.f, 0.f);
            if (grow < NN)
                xv = *reinterpret_cast<const float4*>(x + grow * FIN + k0 + seg * 4);
            Xs[seg * 4 + 0][r] = xv.x;
            Xs[seg * 4 + 1][r] = xv.y;
            Xs[seg * 4 + 2][r] = xv.z;
            Xs[seg * 4 + 3][r] = xv.w;
        }
        // load W tile (16 k x 64 cols, zero-padded past 50)
        {
            int kk = tid >> 4;        // 0..15
            int cs = (tid & 15) * 4;  // 0..60
#pragma unroll
            for (int j = 0; j < 4; j++) {
                int c = cs + j;
                Ws[kk][c] = (c < FH) ? W[(k0 + kk) * FH + c] : 0.f;
            }
        }
        __syncthreads();

#pragma unroll
        for (int kk = 0; kk < 16; kk++) {
            float4 a = *reinterpret_cast<const float4*>(&Xs[kk][ty * 4]);
            float4 w = *reinterpret_cast<const float4*>(&Ws[kk][tx * 4]);
            acc[0][0] += a.x * w.x; acc[0][1] += a.x * w.y; acc[0][2] += a.x * w.z; acc[0][3] += a.x * w.w;
            acc[1][0] += a.y * w.x; acc[1][1] += a.y * w.y; acc[1][2] += a.y * w.z; acc[1][3] += a.y * w.w;
            acc[2][0] += a.z * w.x; acc[2][1] += a.z * w.y; acc[2][2] += a.z * w.z; acc[2][3] += a.z * w.w;
            acc[3][0] += a.w * w.x; acc[3][1] += a.w * w.y; acc[3][2] += a.w * w.z; acc[3][3] += a.w * w.w;
        }
        __syncthreads();
    }

#pragma unroll
    for (int i = 0; i < 4; i++) {
        int grow = rowBase + ty * 4 + i;
        if (grow >= NN) continue;
#pragma unroll
        for (int j = 0; j < 4; j++) {
            int c = tx * 4 + j;
            if (c < FH) g_h1[grow * FHP + c] = acc[i][j] + b[c];
        }
    }
}

// ---------------- aggregation (scatter, vector atomics) ----------------
// layer 1: h = g_h1, out = g_a1, 13 chunks, stride 52
__global__ void agg1_kernel() {
    int t = blockIdx.x * blockDim.x + threadIdx.x;
    if (t >= ET * 13) return;
    int e = t / 13;
    int c = t - e * 13;
    int row = g_row[e], col = g_col[e];
    float nm = g_norm[e];
    float4 v = *reinterpret_cast<const float4*>(g_h1 + row * FHP + c * 4);
    red_add_v4(g_a1 + col * FHP + c * 4,
               make_float4(nm * v.x, nm * v.y, nm * v.z, nm * v.w));
}

// layer 2: h = g_h2, out = d_out, 10 chunks, stride 40
__global__ void agg2_kernel(float* __restrict__ out) {
    int t = blockIdx.x * blockDim.x + threadIdx.x;
    if (t >= ET * 10) return;
    int e = t / 10;
    int c = t - e * 10;
    int row = g_row[e], col = g_col[e];
    float nm = g_norm[e];
    float4 v = *reinterpret_cast<const float4*>(g_h2 + row * FOUT + c * 4);
    red_add_v4(out + col * FOUT + c * 4,
               make_float4(nm * v.x, nm * v.y, nm * v.z, nm * v.w));
}

// ---------------- GEMM2: h2 = relu(a1) @ W2 + b2   (K=50, Ncols=40) ----------------
__global__ void gemm2_kernel(const float* __restrict__ W,
                             const float* __restrict__ b) {
    __shared__ __align__(16) float Ws[FH * FOUT];  // 2000 floats
    __shared__ float bs[FOUT];
    int tid = threadIdx.x;
    for (int i = tid; i < FH * FOUT; i += blockDim.x) Ws[i] = W[i];
    if (tid < FOUT) bs[tid] = b[tid];
    __syncthreads();

    int row = blockIdx.x * blockDim.x + tid;
    if (row >= NN) return;

    float acc[FOUT];
#pragma unroll
    for (int j = 0; j < FOUT; j++) acc[j] = bs[j];

    const float* a1row = g_a1 + row * FHP;
    for (int k = 0; k < FH; k++) {
        float v = fmaxf(a1row[k], 0.f);  // relu
#pragma unroll
        for (int jj = 0; jj < FOUT / 4; jj++) {
            float4 w = *reinterpret_cast<const float4*>(&Ws[k * FOUT + jj * 4]);
            acc[jj * 4 + 0] += v * w.x;
            acc[jj * 4 + 1] += v * w.y;
            acc[jj * 4 + 2] += v * w.z;
            acc[jj * 4 + 3] += v * w.w;
        }
    }
#pragma unroll
    for (int jj = 0; jj < FOUT / 4; jj++) {
        *reinterpret_cast<float4*>(&g_h2[row * FOUT + jj * 4]) =
            make_float4(acc[jj * 4 + 0], acc[jj * 4 + 1], acc[jj * 4 + 2], acc[jj * 4 + 3]);
    }
}

// ---------------- log_softmax over 40 cols, in place on d_out ----------------
__global__ void logsoftmax_kernel(float* __restrict__ out) {
    int row = blockIdx.x * blockDim.x + threadIdx.x;
    if (row >= NN) return;
    float* o = out + row * FOUT;
    float v[FOUT];
#pragma unroll
    for (int jj = 0; jj < FOUT / 4; jj++) {
        float4 t = *reinterpret_cast<const float4*>(o + jj * 4);
        v[jj * 4 + 0] = t.x; v[jj * 4 + 1] = t.y; v[jj * 4 + 2] = t.z; v[jj * 4 + 3] = t.w;
    }
    float m = v[0];
#pragma unroll
    for (int j = 1; j < FOUT; j++) m = fmaxf(m, v[j]);
    float s = 0.f;
#pragma unroll
    for (int j = 0; j < FOUT; j++) s += expf(v[j] - m);
    float l = m + logf(s);
#pragma unroll
    for (int jj = 0; jj < FOUT / 4; jj++) {
        *reinterpret_cast<float4*>(o + jj * 4) =
            make_float4(v[jj * 4 + 0] - l, v[jj * 4 + 1] - l, v[jj * 4 + 2] - l, v[jj * 4 + 3] - l);
    }
}

// ---------------- launch ----------------
extern "C" void kernel_launch(void* const* d_in, const int* in_sizes, int n_in,
                              void* d_out, int out_size) {
    const float* x   = (const float*)d_in[0];
    const int*   ei  = (const int*)d_in[1];   // int32 (JAX x64 disabled)
    const float* W1  = (const float*)d_in[2];
    const float* b1  = (const float*)d_in[3];
    const float* W2  = (const float*)d_in[4];
    const float* b2  = (const float*)d_in[5];
    float*       out = (float*)d_out;

    const int T = 256;

    // zero a1 + deg, and out
    zero_scratch_kernel<<<(NN * FHP / 4 + T - 1) / T, T>>>();
    zero_out_kernel<<<(NN * FOUT / 4 + T - 1) / T, T>>>((float4*)out);

    // graph prep
    prep_kernel<<<(ET + T - 1) / T, T>>>(ei);
    norm_kernel<<<(ET + T - 1) / T, T>>>();

    // layer 1
    gemm1_kernel<<<(NN + 63) / 64, T>>>(x, W1, b1);
    agg1_kernel<<<(ET * 13 + T - 1) / T, T>>>();

    // layer 2
    gemm2_kernel<<<(NN + T - 1) / T, T>>>(W2, b2);
    agg2_kernel<<<(ET * 10 + T - 1) / T, T>>>(out);

    // log softmax
    logsoftmax_kernel<<<(NN + T - 1) / T, T>>>(out);
}

// round 3
// speedup vs baseline: 1.3763x; 1.3763x over previous
#include <cuda_runtime.h>
#include <math.h>

#define NN   100000
#define FIN  256
#define FH   50
#define FHP  52        // padded hidden width (13 float4)
#define FOUT 40        // 10 float4
#define EE   3200000
#define ET   (EE + NN) // edges + self loops

#define SCAN_BS 512
#define SCAN_NB ((NN + SCAN_BS - 1) / SCAN_BS)   // 196

// ---------------- scratch (device globals; no allocation) ----------------
__device__ __align__(16) float g_h1[NN * FHP];   // x@W1+b1  (padded)
__device__ __align__(16) float g_a1[NN * FHP];   // relu(aggregated layer1)
__device__ __align__(16) float g_h2[NN * FOUT];  // a1@W2+b2
__device__ int   g_degi[NN];
__device__ int   g_cursor[NN];
__device__ float g_dinv[NN];
__device__ int   g_off[NN + 1];                  // CSR offsets (exclusive)
__device__ int   g_bsum[SCAN_NB];
__device__ int   g_boff[SCAN_NB];
__device__ int2  g_edge[ET];                     // {row, col}
__device__ int2  g_adj[ET];                      // {row, norm-as-int} grouped by col

// ---------------- zeroing (counts only; a1/out fully overwritten) --------
__global__ void zero_counts_kernel() {
    int i = blockIdx.x * blockDim.x + threadIdx.x;
    if (i < NN) { g_degi[i] = 0; g_cursor[i] = 0; }
}

// ---------------- prep: decode edges, count in-degree --------------------
__global__ void prep_kernel(const int* __restrict__ ei) {
    int e = blockIdx.x * blockDim.x + threadIdx.x;
    if (e >= ET) return;
    int r, c;
    if (e < EE) { r = ei[e]; c = ei[EE + e]; }
    else        { r = c = e - EE; }
    if ((unsigned)r >= NN) r = 0;
    if ((unsigned)c >= NN) c = 0;
    g_edge[e] = make_int2(r, c);
    atomicAdd(&g_degi[c], 1);
}

// ---------------- scan A: per-block sums ----------------------------------
__global__ void scanA_kernel() {
    __shared__ int s[SCAN_BS];
    int tid = threadIdx.x;
    int i = blockIdx.x * SCAN_BS + tid;
    s[tid] = (i < NN) ? g_degi[i] : 0;
    __syncthreads();
    for (int st = SCAN_BS / 2; st > 0; st >>= 1) {
        if (tid < st) s[tid] += s[tid + st];
        __syncthreads();
    }
    if (tid == 0) g_bsum[blockIdx.x] = s[0];
}

// ---------------- scan B: exclusive scan of block sums (tiny) -------------
__global__ void scanB_kernel() {
    int acc = 0;
    for (int i = 0; i < SCAN_NB; i++) {
        g_boff[i] = acc;
        acc += g_bsum[i];
    }
    g_off[NN] = ET;   // total (every edge counted exactly once by col)
}

// ---------------- scan C: in-block exclusive scan + dinv ------------------
__global__ void scanC_kernel() {
    __shared__ int s[SCAN_BS];
    int tid = threadIdx.x;
    int i = blockIdx.x * SCAN_BS + tid;
    int v = (i < NN) ? g_degi[i] : 0;
    s[tid] = v;
    __syncthreads();
    for (int off = 1; off < SCAN_BS; off <<= 1) {
        int t = s[tid];
        if (tid >= off) t += s[tid - off];
        __syncthreads();
        s[tid] = t;
        __syncthreads();
    }
    if (i < NN) {
        g_off[i] = g_boff[blockIdx.x] + s[tid] - v;      // exclusive
        g_dinv[i] = (v > 0) ? rsqrtf((float)v) : 0.f;
    }
}

// ---------------- fill CSR slots: {row, norm} grouped by col ---------------
__global__ void fill_kernel() {
    int e = blockIdx.x * blockDim.x + threadIdx.x;
    if (e >= ET) return;
    int2 rc = g_edge[e];
    float nm = g_dinv[rc.x] * g_dinv[rc.y];
    int pos = atomicAdd(&g_cursor[rc.y], 1);
    g_adj[g_off[rc.y] + pos] = make_int2(rc.x, __float_as_int(nm));
}

// ---------------- GEMM1: h1 = x @ W1 + b1 ---------------------------------
__global__ void gemm1_kernel(const float* __restrict__ x,
                             const float* __restrict__ W,
                             const float* __restrict__ b) {
    __shared__ __align__(16) float Xs[16][68];
    __shared__ __align__(16) float Ws[16][64];

    int tid = threadIdx.x;
    int tx = tid & 15;
    int ty = tid >> 4;
    int rowBase = blockIdx.x * 64;

    float acc[4][4];
#pragma unroll
    for (int i = 0; i < 4; i++)
#pragma unroll
        for (int j = 0; j < 4; j++) acc[i][j] = 0.f;

    for (int k0 = 0; k0 < FIN; k0 += 16) {
        {
            int r = tid >> 2, seg = tid & 3;
            int grow = rowBase + r;
            float4 xv = make_float4(0.f, 0.f, 0.f, 0.f);
            if (grow < NN)
                xv = *reinterpret_cast<const float4*>(x + grow * FIN + k0 + seg * 4);
            Xs[seg * 4 + 0][r] = xv.x;
            Xs[seg * 4 + 1][r] = xv.y;
            Xs[seg * 4 + 2][r] = xv.z;
            Xs[seg * 4 + 3][r] = xv.w;
        }
        {
            int kk = tid >> 4;
            int cs = (tid & 15) * 4;
#pragma unroll
            for (int j = 0; j < 4; j++) {
                int c = cs + j;
                Ws[kk][c] = (c < FH) ? W[(k0 + kk) * FH + c] : 0.f;
            }
        }
        __syncthreads();

#pragma unroll
        for (int kk = 0; kk < 16; kk++) {
            float4 a = *reinterpret_cast<const float4*>(&Xs[kk][ty * 4]);
            float4 w = *reinterpret_cast<const float4*>(&Ws[kk][tx * 4]);
            acc[0][0] += a.x * w.x; acc[0][1] += a.x * w.y; acc[0][2] += a.x * w.z; acc[0][3] += a.x * w.w;
            acc[1][0] += a.y * w.x; acc[1][1] += a.y * w.y; acc[1][2] += a.y * w.z; acc[1][3] += a.y * w.w;
            acc[2][0] += a.z * w.x; acc[2][1] += a.z * w.y; acc[2][2] += a.z * w.z; acc[2][3] += a.z * w.w;
            acc[3][0] += a.w * w.x; acc[3][1] += a.w * w.y; acc[3][2] += a.w * w.z; acc[3][3] += a.w * w.w;
        }
        __syncthreads();
    }

#pragma unroll
    for (int i = 0; i < 4; i++) {
        int grow = rowBase + ty * 4 + i;
        if (grow >= NN) continue;
#pragma unroll
        for (int j = 0; j < 4; j++) {
            int c = tx * 4 + j;
            if (c < FH)       g_h1[grow * FHP + c] = acc[i][j] + b[c];
            else if (c < FHP) g_h1[grow * FHP + c] = 0.f;   // keep pad clean
        }
    }
}

// ---------------- agg1: CSR gather, relu fused into store ------------------
// 16 threads per node; lanes 0..12 own float4 chunks of the 52-wide row.
__global__ void agg1_kernel() {
    int t = blockIdx.x * blockDim.x + threadIdx.x;
    int node = t >> 4;
    int ch = t & 15;
    if (node >= NN || ch >= 13) return;

    int j = g_off[node];
    int end = g_off[node + 1];
    float4 acc = make_float4(0.f, 0.f, 0.f, 0.f);
    float4 acc2 = make_float4(0.f, 0.f, 0.f, 0.f);

    for (; j + 1 < end; j += 2) {
        int2 a0 = g_adj[j];
        int2 a1 = g_adj[j + 1];
        float n0 = __int_as_float(a0.y);
        float n1 = __int_as_float(a1.y);
        float4 v0 = *reinterpret_cast<const float4*>(g_h1 + a0.x * FHP + ch * 4);
        float4 v1 = *reinterpret_cast<const float4*>(g_h1 + a1.x * FHP + ch * 4);
        acc.x  += n0 * v0.x; acc.y  += n0 * v0.y; acc.z  += n0 * v0.z; acc.w  += n0 * v0.w;
        acc2.x += n1 * v1.x; acc2.y += n1 * v1.y; acc2.z += n1 * v1.z; acc2.w += n1 * v1.w;
    }
    if (j < end) {
        int2 a0 = g_adj[j];
        float n0 = __int_as_float(a0.y);
        float4 v0 = *reinterpret_cast<const float4*>(g_h1 + a0.x * FHP + ch * 4);
        acc.x += n0 * v0.x; acc.y += n0 * v0.y; acc.z += n0 * v0.z; acc.w += n0 * v0.w;
    }
    acc.x += acc2.x; acc.y += acc2.y; acc.z += acc2.z; acc.w += acc2.w;

    *reinterpret_cast<float4*>(g_a1 + node * FHP + ch * 4) =
        make_float4(fmaxf(acc.x, 0.f), fmaxf(acc.y, 0.f),
                    fmaxf(acc.z, 0.f), fmaxf(acc.w, 0.f));
}

// ---------------- GEMM2: h2 = a1 @ W2 + b2  (a1 already relu'd) -----------
__global__ void gemm2_kernel(const float* __restrict__ W,
                             const float* __restrict__ b) {
    __shared__ __align__(16) float Ws[FH * FOUT];
    __shared__ float bs[FOUT];
    int tid = threadIdx.x;
    for (int i = tid; i < FH * FOUT; i += blockDim.x) Ws[i] = W[i];
    if (tid < FOUT) bs[tid] = b[tid];
    __syncthreads();

    int row = blockIdx.x * blockDim.x + tid;
    if (row >= NN) return;

    float acc[FOUT];
#pragma unroll
    for (int j = 0; j < FOUT; j++) acc[j] = bs[j];

    const float* a1row = g_a1 + row * FHP;
    for (int k = 0; k < FH; k++) {
        float v = a1row[k];
#pragma unroll
        for (int jj = 0; jj < FOUT / 4; jj++) {
            float4 w = *reinterpret_cast<const float4*>(&Ws[k * FOUT + jj * 4]);
            acc[jj * 4 + 0] += v * w.x;
            acc[jj * 4 + 1] += v * w.y;
            acc[jj * 4 + 2] += v * w.z;
            acc[jj * 4 + 3] += v * w.w;
        }
    }
#pragma unroll
    for (int jj = 0; jj < FOUT / 4; jj++) {
        *reinterpret_cast<float4*>(&g_h2[row * FOUT + jj * 4]) =
            make_float4(acc[jj * 4 + 0], acc[jj * 4 + 1], acc[jj * 4 + 2], acc[jj * 4 + 3]);
    }
}

// ---------------- agg2 + log_softmax fused ---------------------------------
// 16 threads per node; lanes 0..9 own float4 chunks of the 40-wide row.
// All 16 lanes participate in width-16 shuffles (no early return).
__global__ void agg2_ls_kernel(float* __restrict__ out) {
    int t = blockIdx.x * blockDim.x + threadIdx.x;
    int node = t >> 4;
    int ch = t & 15;
    bool valid = (node < NN);
    bool act = valid && (ch < 10);

    float4 acc = make_float4(0.f, 0.f, 0.f, 0.f);
    float4 acc2 = make_float4(0.f, 0.f, 0.f, 0.f);

    if (valid) {
        int j = g_off[node];
        int end = g_off[node + 1];
        if (act) {
            for (; j + 1 < end; j += 2) {
                int2 a0 = g_adj[j];
                int2 a1 = g_adj[j + 1];
                float n0 = __int_as_float(a0.y);
                float n1 = __int_as_float(a1.y);
                float4 v0 = *reinterpret_cast<const float4*>(g_h2 + a0.x * FOUT + ch * 4);
                float4 v1 = *reinterpret_cast<const float4*>(g_h2 + a1.x * FOUT + ch * 4);
                acc.x  += n0 * v0.x; acc.y  += n0 * v0.y; acc.z  += n0 * v0.z; acc.w  += n0 * v0.w;
                acc2.x += n1 * v1.x; acc2.y += n1 * v1.y; acc2.z += n1 * v1.z; acc2.w += n1 * v1.w;
            }
            if (j < end) {
                int2 a0 = g_adj[j];
                float n0 = __int_as_float(a0.y);
                float4 v0 = *reinterpret_cast<const float4*>(g_h2 + a0.x * FOUT + ch * 4);
                acc.x += n0 * v0.x; acc.y += n0 * v0.y; acc.z += n0 * v0.z; acc.w += n0 * v0.w;
            }
        }
    }
    acc.x += acc2.x; acc.y += acc2.y; acc.z += acc2.z; acc.w += acc2.w;

    // row max over the 16-lane group
    float m = act ? fmaxf(fmaxf(acc.x, acc.y), fmaxf(acc.z, acc.w)) : -INFINITY;
#pragma unroll
    for (int d = 8; d > 0; d >>= 1)
        m = fmaxf(m, __shfl_down_sync(0xffffffffu, m, d, 16));
    m = __shfl_sync(0xffffffffu, m, 0, 16);

    float s = act ? (expf(acc.x - m) + expf(acc.y - m) + expf(acc.z - m) + expf(acc.w - m)) : 0.f;
#pragma unroll
    for (int d = 8; d > 0; d >>= 1)
        s += __shfl_down_sync(0xffffffffu, s, d, 16);
    s = __shfl_sync(0xffffffffu, s, 0, 16);

    float l = m + logf(s);
    if (act) {
        *reinterpret_cast<float4*>(out + node * FOUT + ch * 4) =
            make_float4(acc.x - l, acc.y - l, acc.z - l, acc.w - l);
    }
}

// ---------------- launch ----------------
extern "C" void kernel_launch(void* const* d_in, const int* in_sizes, int n_in,
                              void* d_out, int out_size) {
    const float* x   = (const float*)d_in[0];
    const int*   ei  = (const int*)d_in[1];   // int32 (JAX x64 disabled)
    const float* W1  = (const float*)d_in[2];
    const float* b1  = (const float*)d_in[3];
    const float* W2  = (const float*)d_in[4];
    const float* b2  = (const float*)d_in[5];
    float*       out = (float*)d_out;

    const int T = 256;

    zero_counts_kernel<<<(NN + T - 1) / T, T>>>();
    prep_kernel<<<(ET + T - 1) / T, T>>>(ei);
    scanA_kernel<<<SCAN_NB, SCAN_BS>>>();
    scanB_kernel<<<1, 1>>>();
    scanC_kernel<<<SCAN_NB, SCAN_BS>>>();
    fill_kernel<<<(ET + T - 1) / T, T>>>();

    gemm1_kernel<<<(NN + 63) / 64, T>>>(x, W1, b1);
    agg1_kernel<<<(NN * 16 + T - 1) / T, T>>>();

    gemm2_kernel<<<(NN + T - 1) / T, T>>>(W2, b2);
    agg2_ls_kernel<<<(NN * 16 + T - 1) / T, T>>>(out);
}

// round 4
// speedup vs baseline: 1.6882x; 1.2266x over previous
#include <cuda_runtime.h>
#include <math.h>
#include <stdint.h>

#define NN   100000
#define FIN  256
#define FH   50
#define FHP  52        // padded hidden width (13 float4)
#define FOUT 40        // 10 float4
#define EE   3200000
#define ET   (EE + NN) // edges + self loops

#define SCAN_BS 512
#define SCAN_NB ((NN + SCAN_BS - 1) / SCAN_BS)   // 196

// ---------------- scratch (device globals; no allocation) ----------------
__device__ __align__(16) float g_h1[NN * FHP];   // x@W1+b1  (padded, pads zeroed)
__device__ __align__(16) float g_a1[NN * FHP];   // relu(aggregated layer1)
__device__ __align__(16) float g_h2[NN * FOUT];  // a1@W2+b2
__device__ int   g_degi[NN];
__device__ int   g_cursor[NN];                   // seeded to g_off in scanC
__device__ float g_dinv[NN];
__device__ int   g_off[NN + 1];                  // CSR offsets (exclusive)
__device__ int   g_bsum[SCAN_NB];
__device__ int   g_boff[SCAN_NB];
__device__ int2  g_adj[ET];                      // {row, norm-as-int} grouped by col

// ---------------- zeroing ----------------
__global__ void zero_counts_kernel() {
    int i = blockIdx.x * blockDim.x + threadIdx.x;
    if (i < NN) g_degi[i] = 0;
}

// ---------------- prep: count in-degree only ------------------------------
__global__ void prep_kernel(const int* __restrict__ ei) {
    int e = blockIdx.x * blockDim.x + threadIdx.x;
    if (e >= ET) return;
    int c = (e < EE) ? ei[EE + e] : (e - EE);
    if ((unsigned)c >= NN) c = 0;
    atomicAdd(&g_degi[c], 1);
}

// ---------------- scan A: per-block sums ----------------------------------
__global__ void scanA_kernel() {
    __shared__ int s[SCAN_BS];
    int tid = threadIdx.x;
    int i = blockIdx.x * SCAN_BS + tid;
    s[tid] = (i < NN) ? g_degi[i] : 0;
    __syncthreads();
    for (int st = SCAN_BS / 2; st > 0; st >>= 1) {
        if (tid < st) s[tid] += s[tid + st];
        __syncthreads();
    }
    if (tid == 0) g_bsum[blockIdx.x] = s[0];
}

// ---------------- scan B: parallel exclusive scan of block sums ------------
__global__ void scanB_kernel() {
    __shared__ int s[256];
    int tid = threadIdx.x;
    int v = (tid < SCAN_NB) ? g_bsum[tid] : 0;
    s[tid] = v;
    __syncthreads();
    for (int off = 1; off < 256; off <<= 1) {
        int add = (tid >= off) ? s[tid - off] : 0;
        __syncthreads();
        s[tid] += add;
        __syncthreads();
    }
    if (tid < SCAN_NB) g_boff[tid] = s[tid] - v;   // exclusive
    if (tid == 0) g_off[NN] = ET;
}

// ---------------- scan C: in-block exclusive scan + dinv + cursor seed -----
__global__ void scanC_kernel() {
    __shared__ int s[SCAN_BS];
    int tid = threadIdx.x;
    int i = blockIdx.x * SCAN_BS + tid;
    int v = (i < NN) ? g_degi[i] : 0;
    s[tid] = v;
    __syncthreads();
    for (int off = 1; off < SCAN_BS; off <<= 1) {
        int t = s[tid];
        int add = (tid >= off) ? s[tid - off] : 0;
        __syncthreads();
        s[tid] = t + add;
        __syncthreads();
    }
    if (i < NN) {
        int off = g_boff[blockIdx.x] + s[tid] - v;   // exclusive
        g_off[i] = off;
        g_cursor[i] = off;                            // fill uses absolute slots
        g_dinv[i] = (v > 0) ? rsqrtf((float)v) : 0.f;
    }
}

// ---------------- fill CSR slots: {row, norm} grouped by col ---------------
__global__ void fill_kernel(const int* __restrict__ ei) {
    int e = blockIdx.x * blockDim.x + threadIdx.x;
    if (e >= ET) return;
    int r, c;
    if (e < EE) { r = ei[e]; c = ei[EE + e]; }
    else        { r = c = e - EE; }
    if ((unsigned)r >= NN) r = 0;
    if ((unsigned)c >= NN) c = 0;
    float nm = g_dinv[r] * g_dinv[c];
    int pos = atomicAdd(&g_cursor[c], 1);
    g_adj[pos] = make_int2(r, __float_as_int(nm));
}

// ---------------- GEMM1 (tf32 tensor cores): h1 = x @ W1 + b1 --------------
// Block tile 128x64 (cols padded 50->64), BK=16. 8 warps: 4 (M) x 2 (N).
// Each warp: 32x32 = 2 m-tiles x 4 n-tiles of m16n8k8.
__device__ __forceinline__ uint32_t f2tf32(float f) {
    uint32_t u;
    asm("cvt.rna.tf32.f32 %0, %1;" : "=r"(u) : "f"(f));
    return u;
}

__global__ void gemm1_tf32_kernel(const float* __restrict__ x,
                                  const float* __restrict__ W,
                                  const float* __restrict__ b) {
    __shared__ uint32_t Xs[128][20];   // pitch 20: conflict-free frag loads
    __shared__ uint32_t Ws[16][72];    // pitch 72: conflict-free frag loads
    __shared__ float bs[64];

    int tid = threadIdx.x;
    int lane = tid & 31;
    int warp = tid >> 5;
    int wm = warp & 3;            // 0..3 -> m offset 32*wm
    int wn = warp >> 2;           // 0..1 -> n offset 32*wn
    int rowBase = blockIdx.x * 128;

    if (tid < 64) bs[tid] = (tid < FH) ? b[tid] : 0.f;

    float acc[2][4][4];
#pragma unroll
    for (int mt = 0; mt < 2; mt++)
#pragma unroll
        for (int nt = 0; nt < 4; nt++)
#pragma unroll
            for (int q = 0; q < 4; q++) acc[mt][nt][q] = 0.f;

    for (int k0 = 0; k0 < FIN; k0 += 16) {
        // load X tile: 128 rows x 16 k
        {
            int r = tid >> 2;              // 0..63
            int cs = (tid & 3) * 4;        // 0,4,8,12
#pragma unroll
            for (int i = 0; i < 2; i++) {
                int row = i * 64 + r;
                int grow = rowBase + row;
                float4 xv = make_float4(0.f, 0.f, 0.f, 0.f);
                if (grow < NN)
                    xv = *reinterpret_cast<const float4*>(x + grow * FIN + k0 + cs);
                Xs[row][cs + 0] = f2tf32(xv.x);
                Xs[row][cs + 1] = f2tf32(xv.y);
                Xs[row][cs + 2] = f2tf32(xv.z);
                Xs[row][cs + 3] = f2tf32(xv.w);
            }
        }
        // load W tile: 16 k x 64 cols (zero pad past 50)
        {
#pragma unroll
            for (int i = 0; i < 4; i++) {
                int idx = i * 256 + tid;       // 0..1023
                int kk = idx >> 6;
                int c = idx & 63;
                float wv = (c < FH) ? W[(k0 + kk) * FH + c] : 0.f;
                Ws[kk][c] = f2tf32(wv);
            }
        }
        __syncthreads();

#pragma unroll
        for (int ks = 0; ks < 16; ks += 8) {
            // A fragments: 2 m-tiles of 16x8
            uint32_t a[2][4];
#pragma unroll
            for (int mt = 0; mt < 2; mt++) {
                int r = wm * 32 + mt * 16 + (lane >> 2);
                int c = ks + (lane & 3);
                a[mt][0] = Xs[r][c];
                a[mt][1] = Xs[r + 8][c];
                a[mt][2] = Xs[r][c + 4];
                a[mt][3] = Xs[r + 8][c + 4];
            }
#pragma unroll
            for (int nt = 0; nt < 4; nt++) {
                int n = wn * 32 + nt * 8 + (lane >> 2);
                int kb = ks + (lane & 3);
                uint32_t b0 = Ws[kb][n];
                uint32_t b1 = Ws[kb + 4][n];
#pragma unroll
                for (int mt = 0; mt < 2; mt++) {
                    asm volatile(
                        "mma.sync.aligned.m16n8k8.row.col.f32.tf32.tf32.f32 "
                        "{%0,%1,%2,%3}, {%4,%5,%6,%7}, {%8,%9}, {%0,%1,%2,%3};"
                        : "+f"(acc[mt][nt][0]), "+f"(acc[mt][nt][1]),
                          "+f"(acc[mt][nt][2]), "+f"(acc[mt][nt][3])
                        : "r"(a[mt][0]), "r"(a[mt][1]), "r"(a[mt][2]), "r"(a[mt][3]),
                          "r"(b0), "r"(b1));
                }
            }
        }
        __syncthreads();
    }

    // epilogue: c0,c1 at (row, col), (row, col+1); c2,c3 at (row+8, ...)
#pragma unroll
    for (int mt = 0; mt < 2; mt++) {
#pragma unroll
        for (int nt = 0; nt < 4; nt++) {
            int row0 = rowBase + wm * 32 + mt * 16 + (lane >> 2);
            int col0 = wn * 32 + nt * 8 + 2 * (lane & 3);
#pragma unroll
            for (int h = 0; h < 2; h++) {
                int row = row0 + h * 8;
                if (row >= NN) continue;
#pragma unroll
                for (int q = 0; q < 2; q++) {
                    int col = col0 + q;
                    float v = acc[mt][nt][h * 2 + q];
                    if (col < FH)       g_h1[row * FHP + col] = v + bs[col];
                    else if (col < FHP) g_h1[row * FHP + col] = 0.f;
                }
            }
        }
    }
}

// ---------------- agg1: CSR gather, relu fused into store ------------------
__global__ void agg1_kernel() {
    int t = blockIdx.x * blockDim.x + threadIdx.x;
    int node = t >> 4;
    int ch = t & 15;
    if (node >= NN || ch >= 13) return;

    int j = g_off[node];
    int end = g_off[node + 1];
    float4 acc = make_float4(0.f, 0.f, 0.f, 0.f);
    float4 acc2 = make_float4(0.f, 0.f, 0.f, 0.f);

    for (; j + 1 < end; j += 2) {
        int2 a0 = g_adj[j];
        int2 a1 = g_adj[j + 1];
        float n0 = __int_as_float(a0.y);
        float n1 = __int_as_float(a1.y);
        float4 v0 = *reinterpret_cast<const float4*>(g_h1 + a0.x * FHP + ch * 4);
        float4 v1 = *reinterpret_cast<const float4*>(g_h1 + a1.x * FHP + ch * 4);
        acc.x  += n0 * v0.x; acc.y  += n0 * v0.y; acc.z  += n0 * v0.z; acc.w  += n0 * v0.w;
        acc2.x += n1 * v1.x; acc2.y += n1 * v1.y; acc2.z += n1 * v1.z; acc2.w += n1 * v1.w;
    }
    if (j < end) {
        int2 a0 = g_adj[j];
        float n0 = __int_as_float(a0.y);
        float4 v0 = *reinterpret_cast<const float4*>(g_h1 + a0.x * FHP + ch * 4);
        acc.x += n0 * v0.x; acc.y += n0 * v0.y; acc.z += n0 * v0.z; acc.w += n0 * v0.w;
    }
    acc.x += acc2.x; acc.y += acc2.y; acc.z += acc2.z; acc.w += acc2.w;

    *reinterpret_cast<float4*>(g_a1 + node * FHP + ch * 4) =
        make_float4(fmaxf(acc.x, 0.f), fmaxf(acc.y, 0.f),
                    fmaxf(acc.z, 0.f), fmaxf(acc.w, 0.f));
}

// ---------------- GEMM2: h2 = a1 @ W2 + b2  (a1 already relu'd) -----------
__global__ void gemm2_kernel(const float* __restrict__ W,
                             const float* __restrict__ b) {
    __shared__ __align__(16) float Ws[FH * FOUT];
    __shared__ float bs[FOUT];
    int tid = threadIdx.x;
    for (int i = tid; i < FH * FOUT; i += blockDim.x) Ws[i] = W[i];
    if (tid < FOUT) bs[tid] = b[tid];
    __syncthreads();

    int row = blockIdx.x * blockDim.x + tid;
    if (row >= NN) return;

    float acc[FOUT];
#pragma unroll
    for (int j = 0; j < FOUT; j++) acc[j] = bs[j];

    const float* a1row = g_a1 + row * FHP;
    for (int k = 0; k < FH; k++) {
        float v = a1row[k];
#pragma unroll
        for (int jj = 0; jj < FOUT / 4; jj++) {
            float4 w = *reinterpret_cast<const float4*>(&Ws[k * FOUT + jj * 4]);
            acc[jj * 4 + 0] += v * w.x;
            acc[jj * 4 + 1] += v * w.y;
            acc[jj * 4 + 2] += v * w.z;
            acc[jj * 4 + 3] += v * w.w;
        }
    }
#pragma unroll
    for (int jj = 0; jj < FOUT / 4; jj++) {
        *reinterpret_cast<float4*>(&g_h2[row * FOUT + jj * 4]) =
            make_float4(acc[jj * 4 + 0], acc[jj * 4 + 1], acc[jj * 4 + 2], acc[jj * 4 + 3]);
    }
}

// ---------------- agg2 + log_softmax fused ---------------------------------
__global__ void agg2_ls_kernel(float* __restrict__ out) {
    int t = blockIdx.x * blockDim.x + threadIdx.x;
    int node = t >> 4;
    int ch = t & 15;
    bool valid = (node < NN);
    bool act = valid && (ch < 10);

    float4 acc = make_float4(0.f, 0.f, 0.f, 0.f);
    float4 acc2 = make_float4(0.f, 0.f, 0.f, 0.f);

    if (act) {
        int j = g_off[node];
        int end = g_off[node + 1];
        for (; j + 1 < end; j += 2) {
            int2 a0 = g_adj[j];
            int2 a1 = g_adj[j + 1];
            float n0 = __int_as_float(a0.y);
            float n1 = __int_as_float(a1.y);
            float4 v0 = *reinterpret_cast<const float4*>(g_h2 + a0.x * FOUT + ch * 4);
            float4 v1 = *reinterpret_cast<const float4*>(g_h2 + a1.x * FOUT + ch * 4);
            acc.x  += n0 * v0.x; acc.y  += n0 * v0.y; acc.z  += n0 * v0.z; acc.w  += n0 * v0.w;
            acc2.x += n1 * v1.x; acc2.y += n1 * v1.y; acc2.z += n1 * v1.z; acc2.w += n1 * v1.w;
        }
        if (j < end) {
            int2 a0 = g_adj[j];
            float n0 = __int_as_float(a0.y);
            float4 v0 = *reinterpret_cast<const float4*>(g_h2 + a0.x * FOUT + ch * 4);
            acc.x += n0 * v0.x; acc.y += n0 * v0.y; acc.z += n0 * v0.z; acc.w += n0 * v0.w;
        }
    }
    acc.x += acc2.x; acc.y += acc2.y; acc.z += acc2.z; acc.w += acc2.w;

    float m = act ? fmaxf(fmaxf(acc.x, acc.y), fmaxf(acc.z, acc.w)) : -INFINITY;
#pragma unroll
    for (int d = 8; d > 0; d >>= 1)
        m = fmaxf(m, __shfl_down_sync(0xffffffffu, m, d, 16));
    m = __shfl_sync(0xffffffffu, m, 0, 16);

    float s = act ? (expf(acc.x - m) + expf(acc.y - m) + expf(acc.z - m) + expf(acc.w - m)) : 0.f;
#pragma unroll
    for (int d = 8; d > 0; d >>= 1)
        s += __shfl_down_sync(0xffffffffu, s, d, 16);
    s = __shfl_sync(0xffffffffu, s, 0, 16);

    float l = m + logf(s);
    if (act) {
        *reinterpret_cast<float4*>(out + node * FOUT + ch * 4) =
            make_float4(acc.x - l, acc.y - l, acc.z - l, acc.w - l);
    }
}

// ---------------- launch ----------------
extern "C" void kernel_launch(void* const* d_in, const int* in_sizes, int n_in,
                              void* d_out, int out_size) {
    const float* x   = (const float*)d_in[0];
    const int*   ei  = (const int*)d_in[1];   // int32 (JAX x64 disabled)
    const float* W1  = (const float*)d_in[2];
    const float* b1  = (const float*)d_in[3];
    const float* W2  = (const float*)d_in[4];
    const float* b2  = (const float*)d_in[5];
    float*       out = (float*)d_out;

    const int T = 256;

    zero_counts_kernel<<<(NN + T - 1) / T, T>>>();
    prep_kernel<<<(ET + T - 1) / T, T>>>(ei);
    scanA_kernel<<<SCAN_NB, SCAN_BS>>>();
    scanB_kernel<<<1, 256>>>();
    scanC_kernel<<<SCAN_NB, SCAN_BS>>>();
    fill_kernel<<<(ET + T - 1) / T, T>>>(ei);

    gemm1_tf32_kernel<<<(NN + 127) / 128, T>>>(x, W1, b1);
    agg1_kernel<<<(NN * 16 + T - 1) / T, T>>>();

    gemm2_kernel<<<(NN + T - 1) / T, T>>>(W2, b2);
    agg2_ls_kernel<<<(NN * 16 + T - 1) / T, T>>>(out);
}

// round 7
// speedup vs baseline: 1.7387x; 1.0300x over previous
#include <cuda_runtime.h>
#include <math.h>
#include <stdint.h>

#define NN   100000
#define FIN  256
#define FH   50
#define FHP  52        // padded hidden width (13 float4)
#define FOUT 40        // 10 float4
#define EE   3200000
#define ET   (EE + NN) // edges + self loops

#define SCAN_BS 512
#define SCAN_NB ((NN + SCAN_BS - 1) / SCAN_BS)   // 196

// ---------------- scratch (device globals; no allocation) ----------------
__device__ __align__(16) float g_h1[NN * FHP];   // x@W1+b1  (padded, pads zeroed)
__device__ __align__(16) float g_a1[NN * FHP];   // relu(aggregated layer1)
__device__ __align__(16) float g_h2[NN * FOUT];  // a1@W2+b2
__device__ int   g_degi[NN];
__device__ int   g_cursor[NN];                   // seeded to g_off in scanC
__device__ float g_dinv[NN];
__device__ int   g_off[NN + 1];                  // CSR offsets (exclusive)
__device__ int   g_bsum[SCAN_NB];
__device__ int   g_boff[SCAN_NB];
__device__ int2  g_adj[ET];                      // {row, norm-as-int} grouped by col

// ---------------- degree init: 1 per node (self-loop pre-counted) ---------
__global__ void ones_kernel() {
    int i = blockIdx.x * blockDim.x + threadIdx.x;
    if (i < NN) g_degi[i] = 1;
}

// ---------------- prep: count in-degree of real edges (4 per thread) ------
__global__ void prep_kernel(const int* __restrict__ ei) {
    int t = blockIdx.x * blockDim.x + threadIdx.x;
    if (t >= EE / 4) return;
    int4 c4 = *reinterpret_cast<const int4*>(ei + EE + 4 * t);
    int c;
    c = c4.x; if ((unsigned)c >= NN) c = 0; atomicAdd(&g_degi[c], 1);
    c = c4.y; if ((unsigned)c >= NN) c = 0; atomicAdd(&g_degi[c], 1);
    c = c4.z; if ((unsigned)c >= NN) c = 0; atomicAdd(&g_degi[c], 1);
    c = c4.w; if ((unsigned)c >= NN) c = 0; atomicAdd(&g_degi[c], 1);
}

// ---------------- scan A: per-block sums ----------------------------------
__global__ void scanA_kernel() {
    __shared__ int s[SCAN_BS];
    int tid = threadIdx.x;
    int i = blockIdx.x * SCAN_BS + tid;
    s[tid] = (i < NN) ? g_degi[i] : 0;
    __syncthreads();
    for (int st = SCAN_BS / 2; st > 0; st >>= 1) {
        if (tid < st) s[tid] += s[tid + st];
        __syncthreads();
    }
    if (tid == 0) g_bsum[blockIdx.x] = s[0];
}

// ---------------- scan B: parallel exclusive scan of block sums ------------
__global__ void scanB_kernel() {
    __shared__ int s[256];
    int tid = threadIdx.x;
    int v = (tid < SCAN_NB) ? g_bsum[tid] : 0;
    s[tid] = v;
    __syncthreads();
    for (int off = 1; off < 256; off <<= 1) {
        int add = (tid >= off) ? s[tid - off] : 0;
        __syncthreads();
        s[tid] += add;
        __syncthreads();
    }
    if (tid < SCAN_NB) g_boff[tid] = s[tid] - v;   // exclusive
    if (tid == 0) g_off[NN] = ET;
}

// ---------------- scan C: in-block exclusive scan + dinv + cursor seed -----
__global__ void scanC_kernel() {
    __shared__ int s[SCAN_BS];
    int tid = threadIdx.x;
    int i = blockIdx.x * SCAN_BS + tid;
    int v = (i < NN) ? g_degi[i] : 0;
    s[tid] = v;
    __syncthreads();
    for (int off = 1; off < SCAN_BS; off <<= 1) {
        int t = s[tid];
        int add = (tid >= off) ? s[tid - off] : 0;
        __syncthreads();
        s[tid] = t + add;
        __syncthreads();
    }
    if (i < NN) {
        int off = g_boff[blockIdx.x] + s[tid] - v;   // exclusive
        g_off[i] = off;
        g_cursor[i] = off;                            // fill uses absolute slots
        g_dinv[i] = rsqrtf((float)v);                 // v >= 1 (self-loop)
    }
}

// ---------------- fill CSR slots: {row, norm} grouped by col ---------------
__global__ void fill_kernel(const int* __restrict__ ei) {
    int e = blockIdx.x * blockDim.x + threadIdx.x;
    if (e >= ET) return;
    int r, c;
    if (e < EE) { r = ei[e]; c = ei[EE + e]; }
    else        { r = c = e - EE; }
    if ((unsigned)r >= NN) r = 0;
    if ((unsigned)c >= NN) c = 0;
    float nm = g_dinv[r] * g_dinv[c];
    int pos = atomicAdd(&g_cursor[c], 1);
    g_adj[pos] = make_int2(r, __float_as_int(nm));
}

// ---------------- GEMM1 (tf32 tensor cores): h1 = x @ W1 + b1 --------------
__device__ __forceinline__ uint32_t f2tf32(float f) {
    uint32_t u;
    asm("cvt.rna.tf32.f32 %0, %1;" : "=r"(u) : "f"(f));
    return u;
}

__global__ void gemm1_tf32_kernel(const float* __restrict__ x,
                                  const float* __restrict__ W,
                                  const float* __restrict__ b) {
    __shared__ uint32_t Xs[128][20];   // pitch 20: conflict-free frag loads
    __shared__ uint32_t Ws[16][72];    // pitch 72: conflict-free frag loads
    __shared__ float bs[64];

    int tid = threadIdx.x;
    int lane = tid & 31;
    int warp = tid >> 5;
    int wm = warp & 3;
    int wn = warp >> 2;
    int rowBase = blockIdx.x * 128;

    if (tid < 64) bs[tid] = (tid < FH) ? b[tid] : 0.f;

    float acc[2][4][4];
#pragma unroll
    for (int mt = 0; mt < 2; mt++)
#pragma unroll
        for (int nt = 0; nt < 4; nt++)
#pragma unroll
            for (int q = 0; q < 4; q++) acc[mt][nt][q] = 0.f;

    for (int k0 = 0; k0 < FIN; k0 += 16) {
        {
            int r = tid >> 2;
            int cs = (tid & 3) * 4;
#pragma unroll
            for (int i = 0; i < 2; i++) {
                int row = i * 64 + r;
                int grow = rowBase + row;
                float4 xv = make_float4(0.f, 0.f, 0.f, 0.f);
                if (grow < NN)
                    xv = *reinterpret_cast<const float4*>(x + grow * FIN + k0 + cs);
                Xs[row][cs + 0] = f2tf32(xv.x);
                Xs[row][cs + 1] = f2tf32(xv.y);
                Xs[row][cs + 2] = f2tf32(xv.z);
                Xs[row][cs + 3] = f2tf32(xv.w);
            }
        }
        {
#pragma unroll
            for (int i = 0; i < 4; i++) {
                int idx = i * 256 + tid;
                int kk = idx >> 6;
                int c = idx & 63;
                float wv = (c < FH) ? W[(k0 + kk) * FH + c] : 0.f;
                Ws[kk][c] = f2tf32(wv);
            }
        }
        __syncthreads();

#pragma unroll
        for (int ks = 0; ks < 16; ks += 8) {
            uint32_t a[2][4];
#pragma unroll
            for (int mt = 0; mt < 2; mt++) {
                int r = wm * 32 + mt * 16 + (lane >> 2);
                int c = ks + (lane & 3);
                a[mt][0] = Xs[r][c];
                a[mt][1] = Xs[r + 8][c];
                a[mt][2] = Xs[r][c + 4];
                a[mt][3] = Xs[r + 8][c + 4];
            }
#pragma unroll
            for (int nt = 0; nt < 4; nt++) {
                int n = wn * 32 + nt * 8 + (lane >> 2);
                int kb = ks + (lane & 3);
                uint32_t b0 = Ws[kb][n];
                uint32_t b1 = Ws[kb + 4][n];
#pragma unroll
                for (int mt = 0; mt < 2; mt++) {
                    asm volatile(
                        "mma.sync.aligned.m16n8k8.row.col.f32.tf32.tf32.f32 "
                        "{%0,%1,%2,%3}, {%4,%5,%6,%7}, {%8,%9}, {%0,%1,%2,%3};"
                        : "+f"(acc[mt][nt][0]), "+f"(acc[mt][nt][1]),
                          "+f"(acc[mt][nt][2]), "+f"(acc[mt][nt][3])
                        : "r"(a[mt][0]), "r"(a[mt][1]), "r"(a[mt][2]), "r"(a[mt][3]),
                          "r"(b0), "r"(b1));
                }
            }
        }
        __syncthreads();
    }

#pragma unroll
    for (int mt = 0; mt < 2; mt++) {
#pragma unroll
        for (int nt = 0; nt < 4; nt++) {
            int row0 = rowBase + wm * 32 + mt * 16 + (lane >> 2);
            int col0 = wn * 32 + nt * 8 + 2 * (lane & 3);
#pragma unroll
            for (int h = 0; h < 2; h++) {
                int row = row0 + h * 8;
                if (row >= NN) continue;
#pragma unroll
                for (int q = 0; q < 2; q++) {
                    int col = col0 + q;
                    float v = acc[mt][nt][h * 2 + q];
                    if (col < FH)       g_h1[row * FHP + col] = v + bs[col];
                    else if (col < FHP) g_h1[row * FHP + col] = 0.f;
                }
            }
        }
    }
}

// ---------------- agg1: CSR gather, relu fused into store ------------------
__global__ void agg1_kernel() {
    int t = blockIdx.x * blockDim.x + threadIdx.x;
    int node = t >> 4;
    int ch = t & 15;
    if (node >= NN || ch >= 13) return;

    int j = g_off[node];
    int end = g_off[node + 1];
    float4 acc = make_float4(0.f, 0.f, 0.f, 0.f);
    float4 acc2 = make_float4(0.f, 0.f, 0.f, 0.f);

    for (; j + 1 < end; j += 2) {
        int2 a0 = g_adj[j];
        int2 a1 = g_adj[j + 1];
        float n0 = __int_as_float(a0.y);
        float n1 = __int_as_float(a1.y);
        float4 v0 = *reinterpret_cast<const float4*>(g_h1 + a0.x * FHP + ch * 4);
        float4 v1 = *reinterpret_cast<const float4*>(g_h1 + a1.x * FHP + ch * 4);
        acc.x  += n0 * v0.x; acc.y  += n0 * v0.y; acc.z  += n0 * v0.z; acc.w  += n0 * v0.w;
        acc2.x += n1 * v1.x; acc2.y += n1 * v1.y; acc2.z += n1 * v1.z; acc2.w += n1 * v1.w;
    }
    if (j < end) {
        int2 a0 = g_adj[j];
        float n0 = __int_as_float(a0.y);
        float4 v0 = *reinterpret_cast<const float4*>(g_h1 + a0.x * FHP + ch * 4);
        acc.x += n0 * v0.x; acc.y += n0 * v0.y; acc.z += n0 * v0.z; acc.w += n0 * v0.w;
    }
    acc.x += acc2.x; acc.y += acc2.y; acc.z += acc2.z; acc.w += acc2.w;

    *reinterpret_cast<float4*>(g_a1 + node * FHP + ch * 4) =
        make_float4(fmaxf(acc.x, 0.f), fmaxf(acc.y, 0.f),
                    fmaxf(acc.z, 0.f), fmaxf(acc.w, 0.f));
}

// ---------------- GEMM2: h2 = a1 @ W2 + b2  (float4 a1 loads) --------------
__global__ void gemm2_kernel(const float* __restrict__ W,
                             const float* __restrict__ b) {
    __shared__ __align__(16) float Ws[FH * FOUT];
    __shared__ float bs[FOUT];
    int tid = threadIdx.x;
    for (int i = tid; i < FH * FOUT; i += blockDim.x) Ws[i] = W[i];
    if (tid < FOUT) bs[tid] = b[tid];
    __syncthreads();

    int row = blockIdx.x * blockDim.x + tid;
    if (row >= NN) return;

    float acc[FOUT];
#pragma unroll
    for (int j = 0; j < FOUT; j++) acc[j] = bs[j];

    const float* a1row = g_a1 + row * FHP;
#pragma unroll
    for (int kk = 0; kk < 13; kk++) {   // 13 float4 = 52 (pads are zero)
        float4 a = *reinterpret_cast<const float4*>(a1row + kk * 4);
        float av[4] = {a.x, a.y, a.z, a.w};
#pragma unroll
        for (int q = 0; q < 4; q++) {
            int k = kk * 4 + q;
            if (k >= FH) break;
            float v = av[q];
#pragma unroll
            for (int jj = 0; jj < FOUT / 4; jj++) {
                float4 w = *reinterpret_cast<const float4*>(&Ws[k * FOUT + jj * 4]);
                acc[jj * 4 + 0] += v * w.x;
                acc[jj * 4 + 1] += v * w.y;
                acc[jj * 4 + 2] += v * w.z;
                acc[jj * 4 + 3] += v * w.w;
            }
        }
    }
#pragma unroll
    for (int jj = 0; jj < FOUT / 4; jj++) {
        *reinterpret_cast<float4*>(&g_h2[row * FOUT + jj * 4]) =
            make_float4(acc[jj * 4 + 0], acc[jj * 4 + 1], acc[jj * 4 + 2], acc[jj * 4 + 3]);
    }
}

// ---------------- agg2 + log_softmax fused ---------------------------------
__global__ void agg2_ls_kernel(float* __restrict__ out) {
    int t = blockIdx.x * blockDim.x + threadIdx.x;
    int node = t >> 4;
    int ch = t & 15;
    bool valid = (node < NN);
    bool act = valid && (ch < 10);

    float4 acc = make_float4(0.f, 0.f, 0.f, 0.f);
    float4 acc2 = make_float4(0.f, 0.f, 0.f, 0.f);

    if (act) {
        int j = g_off[node];
        int end = g_off[node + 1];
        for (; j + 1 < end; j += 2) {
            int2 a0 = g_adj[j];
            int2 a1 = g_adj[j + 1];
            float n0 = __int_as_float(a0.y);
            float n1 = __int_as_float(a1.y);
            float4 v0 = *reinterpret_cast<const float4*>(g_h2 + a0.x * FOUT + ch * 4);
            float4 v1 = *reinterpret_cast<const float4*>(g_h2 + a1.x * FOUT + ch * 4);
            acc.x  += n0 * v0.x; acc.y  += n0 * v0.y; acc.z  += n0 * v0.z; acc.w  += n0 * v0.w;
            acc2.x += n1 * v1.x; acc2.y += n1 * v1.y; acc2.z += n1 * v1.z; acc2.w += n1 * v1.w;
        }
        if (j < end) {
            int2 a0 = g_adj[j];
            float n0 = __int_as_float(a0.y);
            float4 v0 = *reinterpret_cast<const float4*>(g_h2 + a0.x * FOUT + ch * 4);
            acc.x += n0 * v0.x; acc.y += n0 * v0.y; acc.z += n0 * v0.z; acc.w += n0 * v0.w;
        }
    }
    acc.x += acc2.x; acc.y += acc2.y; acc.z += acc2.z; acc.w += acc2.w;

    float m = act ? fmaxf(fmaxf(acc.x, acc.y), fmaxf(acc.z, acc.w)) : -INFINITY;
#pragma unroll
    for (int d = 8; d > 0; d >>= 1)
        m = fmaxf(m, __shfl_down_sync(0xffffffffu, m, d, 16));
    m = __shfl_sync(0xffffffffu, m, 0, 16);

    float s = act ? (expf(acc.x - m) + expf(acc.y - m) + expf(acc.z - m) + expf(acc.w - m)) : 0.f;
#pragma unroll
    for (int d = 8; d > 0; d >>= 1)
        s += __shfl_down_sync(0xffffffffu, s, d, 16);
    s = __shfl_sync(0xffffffffu, s, 0, 16);

    float l = m + logf(s);
    if (act) {
        *reinterpret_cast<float4*>(out + node * FOUT + ch * 4) =
            make_float4(acc.x - l, acc.y - l, acc.z - l, acc.w - l);
    }
}

// ---------------- launch (single stream — fork/join breaks this harness) ---
extern "C" void kernel_launch(void* const* d_in, const int* in_sizes, int n_in,
                              void* d_out, int out_size) {
    const float* x   = (const float*)d_in[0];
    const int*   ei  = (const int*)d_in[1];   // int32 (JAX x64 disabled)
    const float* W1  = (const float*)d_in[2];
    const float* b1  = (const float*)d_in[3];
    const float* W2  = (const float*)d_in[4];
    const float* b2  = (const float*)d_in[5];
    float*       out = (float*)d_out;

    const int T = 256;

    // CSR build
    ones_kernel<<<(NN + T - 1) / T, T>>>();
    prep_kernel<<<(EE / 4 + T - 1) / T, T>>>(ei);
    scanA_kernel<<<SCAN_NB, SCAN_BS>>>();
    scanB_kernel<<<1, 256>>>();
    scanC_kernel<<<SCAN_NB, SCAN_BS>>>();
    fill_kernel<<<(ET + T - 1) / T, T>>>(ei);

    // layer 1
    gemm1_tf32_kernel<<<(NN + 127) / 128, T>>>(x, W1, b1);
    agg1_kernel<<<(NN * 16 + T - 1) / T, T>>>();

    // layer 2
    gemm2_kernel<<<(NN + T - 1) / T, T>>>(W2, b2);
    agg2_ls_kernel<<<(NN * 16 + T - 1) / T, T>>>(out);
}

// round 8
// speedup vs baseline: 2.0636x; 1.1869x over previous
#include <cuda_runtime.h>
#include <cuda_fp16.h>
#include <math.h>
#include <stdint.h>

#define NN   100000
#define FIN  256
#define FH   50
#define FHP  52        // padded hidden width
#define FOUT 40
#define EE   3200000
#define ET   (EE + NN) // edges + self loops

#define SCAN_BS 512
#define SCAN_NB ((NN + SCAN_BS - 1) / SCAN_BS)   // 196

// ---------------- scratch (device globals; no allocation) ----------------
__device__ __align__(16) __half g_h1h[NN * FHP]; // x@W1+b1 in fp16 (pads zero)
__device__ __align__(16) float  g_a1[NN * FHP];  // relu(agg layer1), fp32
__device__ __align__(16) __half g_h2h[NN * FOUT];// a1@W2+b2 in fp16
__device__ int   g_degi[NN];
__device__ int   g_cursor[NN];                   // seeded to g_off in scanC
__device__ float g_dinv[NN];
__device__ int   g_off[NN + 1];                  // CSR offsets (exclusive)
__device__ int   g_bsum[SCAN_NB];
__device__ int   g_boff[SCAN_NB];
__device__ int   g_adj[ET];                      // source row only (4B/edge)

// ---------------- degree init: 1 per node (self-loop pre-counted) ---------
__global__ void ones_kernel() {
    int i = blockIdx.x * blockDim.x + threadIdx.x;
    if (i < NN) g_degi[i] = 1;
}

// ---------------- prep: count in-degree of real edges (4 per thread) ------
__global__ void prep_kernel(const int* __restrict__ ei) {
    int t = blockIdx.x * blockDim.x + threadIdx.x;
    if (t >= EE / 4) return;
    int4 c4 = *reinterpret_cast<const int4*>(ei + EE + 4 * t);
    int c;
    c = c4.x; if ((unsigned)c >= NN) c = 0; atomicAdd(&g_degi[c], 1);
    c = c4.y; if ((unsigned)c >= NN) c = 0; atomicAdd(&g_degi[c], 1);
    c = c4.z; if ((unsigned)c >= NN) c = 0; atomicAdd(&g_degi[c], 1);
    c = c4.w; if ((unsigned)c >= NN) c = 0; atomicAdd(&g_degi[c], 1);
}

// ---------------- scan A: per-block sums ----------------------------------
__global__ void scanA_kernel() {
    __shared__ int s[SCAN_BS];
    int tid = threadIdx.x;
    int i = blockIdx.x * SCAN_BS + tid;
    s[tid] = (i < NN) ? g_degi[i] : 0;
    __syncthreads();
    for (int st = SCAN_BS / 2; st > 0; st >>= 1) {
        if (tid < st) s[tid] += s[tid + st];
        __syncthreads();
    }
    if (tid == 0) g_bsum[blockIdx.x] = s[0];
}

// ---------------- scan B: parallel exclusive scan of block sums ------------
__global__ void scanB_kernel() {
    __shared__ int s[256];
    int tid = threadIdx.x;
    int v = (tid < SCAN_NB) ? g_bsum[tid] : 0;
    s[tid] = v;
    __syncthreads();
    for (int off = 1; off < 256; off <<= 1) {
        int add = (tid >= off) ? s[tid - off] : 0;
        __syncthreads();
        s[tid] += add;
        __syncthreads();
    }
    if (tid < SCAN_NB) g_boff[tid] = s[tid] - v;   // exclusive
    if (tid == 0) g_off[NN] = ET;
}

// ---------------- scan C: in-block exclusive scan + dinv + cursor seed -----
__global__ void scanC_kernel() {
    __shared__ int s[SCAN_BS];
    int tid = threadIdx.x;
    int i = blockIdx.x * SCAN_BS + tid;
    int v = (i < NN) ? g_degi[i] : 0;
    s[tid] = v;
    __syncthreads();
    for (int off = 1; off < SCAN_BS; off <<= 1) {
        int t = s[tid];
        int add = (tid >= off) ? s[tid - off] : 0;
        __syncthreads();
        s[tid] = t + add;
        __syncthreads();
    }
    if (i < NN) {
        int off = g_boff[blockIdx.x] + s[tid] - v;   // exclusive
        g_off[i] = off;
        g_cursor[i] = off;                            // fill uses absolute slots
        g_dinv[i] = rsqrtf((float)v);                 // v >= 1 (self-loop)
    }
}

// ---------------- fill CSR slots: source row grouped by col ----------------
__global__ void fill_kernel(const int* __restrict__ ei) {
    int e = blockIdx.x * blockDim.x + threadIdx.x;
    if (e >= ET) return;
    int r, c;
    if (e < EE) { r = ei[e]; c = ei[EE + e]; }
    else        { r = c = e - EE; }
    if ((unsigned)r >= NN) r = 0;
    if ((unsigned)c >= NN) c = 0;
    int pos = atomicAdd(&g_cursor[c], 1);
    g_adj[pos] = r;
}

// ---------------- GEMM1 (tf32 tensor cores): h1 = x @ W1 + b1 (fp16 out) ---
__device__ __forceinline__ uint32_t f2tf32(float f) {
    uint32_t u;
    asm("cvt.rna.tf32.f32 %0, %1;" : "=r"(u) : "f"(f));
    return u;
}

__global__ void gemm1_tf32_kernel(const float* __restrict__ x,
                                  const float* __restrict__ W,
                                  const float* __restrict__ b) {
    __shared__ uint32_t Xs[128][20];   // pitch 20: conflict-free frag loads
    __shared__ uint32_t Ws[16][72];    // pitch 72: conflict-free frag loads
    __shared__ float bs[64];

    int tid = threadIdx.x;
    int lane = tid & 31;
    int warp = tid >> 5;
    int wm = warp & 3;
    int wn = warp >> 2;
    int rowBase = blockIdx.x * 128;

    if (tid < 64) bs[tid] = (tid < FH) ? b[tid] : 0.f;

    float acc[2][4][4];
#pragma unroll
    for (int mt = 0; mt < 2; mt++)
#pragma unroll
        for (int nt = 0; nt < 4; nt++)
#pragma unroll
            for (int q = 0; q < 4; q++) acc[mt][nt][q] = 0.f;

    for (int k0 = 0; k0 < FIN; k0 += 16) {
        {
            int r = tid >> 2;
            int cs = (tid & 3) * 4;
#pragma unroll
            for (int i = 0; i < 2; i++) {
                int row = i * 64 + r;
                int grow = rowBase + row;
                float4 xv = make_float4(0.f, 0.f, 0.f, 0.f);
                if (grow < NN)
                    xv = *reinterpret_cast<const float4*>(x + grow * FIN + k0 + cs);
                Xs[row][cs + 0] = f2tf32(xv.x);
                Xs[row][cs + 1] = f2tf32(xv.y);
                Xs[row][cs + 2] = f2tf32(xv.z);
                Xs[row][cs + 3] = f2tf32(xv.w);
            }
        }
        {
#pragma unroll
            for (int i = 0; i < 4; i++) {
                int idx = i * 256 + tid;
                int kk = idx >> 6;
                int c = idx & 63;
                float wv = (c < FH) ? W[(k0 + kk) * FH + c] : 0.f;
                Ws[kk][c] = f2tf32(wv);
            }
        }
        __syncthreads();

#pragma unroll
        for (int ks = 0; ks < 16; ks += 8) {
            uint32_t a[2][4];
#pragma unroll
            for (int mt = 0; mt < 2; mt++) {
                int r = wm * 32 + mt * 16 + (lane >> 2);
                int c = ks + (lane & 3);
                a[mt][0] = Xs[r][c];
                a[mt][1] = Xs[r + 8][c];
                a[mt][2] = Xs[r][c + 4];
                a[mt][3] = Xs[r + 8][c + 4];
            }
#pragma unroll
            for (int nt = 0; nt < 4; nt++) {
                int n = wn * 32 + nt * 8 + (lane >> 2);
                int kb = ks + (lane & 3);
                uint32_t b0 = Ws[kb][n];
                uint32_t b1 = Ws[kb + 4][n];
#pragma unroll
                for (int mt = 0; mt < 2; mt++) {
                    asm volatile(
                        "mma.sync.aligned.m16n8k8.row.col.f32.tf32.tf32.f32 "
                        "{%0,%1,%2,%3}, {%4,%5,%6,%7}, {%8,%9}, {%0,%1,%2,%3};"
                        : "+f"(acc[mt][nt][0]), "+f"(acc[mt][nt][1]),
                          "+f"(acc[mt][nt][2]), "+f"(acc[mt][nt][3])
                        : "r"(a[mt][0]), "r"(a[mt][1]), "r"(a[mt][2]), "r"(a[mt][3]),
                          "r"(b0), "r"(b1));
                }
            }
        }
        __syncthreads();
    }

    // epilogue: packed half2 stores; cols are even pairs so 50-boundary is clean
#pragma unroll
    for (int mt = 0; mt < 2; mt++) {
#pragma unroll
        for (int nt = 0; nt < 4; nt++) {
            int row0 = rowBase + wm * 32 + mt * 16 + (lane >> 2);
            int col0 = wn * 32 + nt * 8 + 2 * (lane & 3);   // even
            if (col0 >= FHP) continue;
#pragma unroll
            for (int h = 0; h < 2; h++) {
                int row = row0 + h * 8;
                if (row >= NN) continue;
                __half2 hv;
                if (col0 < FH) {
                    hv = __floats2half2_rn(acc[mt][nt][h * 2 + 0] + bs[col0],
                                           acc[mt][nt][h * 2 + 1] + bs[col0 + 1]);
                } else {
                    hv = __floats2half2_rn(0.f, 0.f);       // pad cols 50,51
                }
                *reinterpret_cast<__half2*>(g_h1h + row * FHP + col0) = hv;
            }
        }
    }
}

// ---------------- agg1: CSR gather (fp16 rows), dinv[node] folded out ------
// 16 threads per node; lanes 0..12 own half4 chunks of the 52-wide row.
__global__ void agg1_kernel() {
    int t = blockIdx.x * blockDim.x + threadIdx.x;
    int node = t >> 4;
    int ch = t & 15;
    if (node >= NN || ch >= 13) return;

    int j = g_off[node];
    int end = g_off[node + 1];
    float4 acc = make_float4(0.f, 0.f, 0.f, 0.f);
    float4 acc2 = make_float4(0.f, 0.f, 0.f, 0.f);

    for (; j + 1 < end; j += 2) {
        int r0 = g_adj[j];
        int r1 = g_adj[j + 1];
        float d0 = g_dinv[r0];               // same addr across lanes: broadcast
        float d1 = g_dinv[r1];
        uint2 u0 = *reinterpret_cast<const uint2*>(g_h1h + r0 * FHP + ch * 4);
        uint2 u1 = *reinterpret_cast<const uint2*>(g_h1h + r1 * FHP + ch * 4);
        float2 a0 = __half22float2(*reinterpret_cast<__half2*>(&u0.x));
        float2 b0 = __half22float2(*reinterpret_cast<__half2*>(&u0.y));
        float2 a1 = __half22float2(*reinterpret_cast<__half2*>(&u1.x));
        float2 b1 = __half22float2(*reinterpret_cast<__half2*>(&u1.y));
        acc.x  += d0 * a0.x; acc.y  += d0 * a0.y; acc.z  += d0 * b0.x; acc.w  += d0 * b0.y;
        acc2.x += d1 * a1.x; acc2.y += d1 * a1.y; acc2.z += d1 * b1.x; acc2.w += d1 * b1.y;
    }
    if (j < end) {
        int r0 = g_adj[j];
        float d0 = g_dinv[r0];
        uint2 u0 = *reinterpret_cast<const uint2*>(g_h1h + r0 * FHP + ch * 4);
        float2 a0 = __half22float2(*reinterpret_cast<__half2*>(&u0.x));
        float2 b0 = __half22float2(*reinterpret_cast<__half2*>(&u0.y));
        acc.x += d0 * a0.x; acc.y += d0 * a0.y; acc.z += d0 * b0.x; acc.w += d0 * b0.y;
    }
    acc.x += acc2.x; acc.y += acc2.y; acc.z += acc2.z; acc.w += acc2.w;

    float dc = g_dinv[node];
    *reinterpret_cast<float4*>(g_a1 + node * FHP + ch * 4) =
        make_float4(fmaxf(dc * acc.x, 0.f), fmaxf(dc * acc.y, 0.f),
                    fmaxf(dc * acc.z, 0.f), fmaxf(dc * acc.w, 0.f));
}

// ---------------- GEMM2: h2 = a1 @ W2 + b2  (fp16 out, packed) -------------
__global__ void gemm2_kernel(const float* __restrict__ W,
                             const float* __restrict__ b) {
    __shared__ __align__(16) float Ws[FH * FOUT];
    __shared__ float bs[FOUT];
    int tid = threadIdx.x;
    for (int i = tid; i < FH * FOUT; i += blockDim.x) Ws[i] = W[i];
    if (tid < FOUT) bs[tid] = b[tid];
    __syncthreads();

    int row = blockIdx.x * blockDim.x + tid;
    if (row >= NN) return;

    float acc[FOUT];
#pragma unroll
    for (int j = 0; j < FOUT; j++) acc[j] = bs[j];

    const float* a1row = g_a1 + row * FHP;
#pragma unroll
    for (int kk = 0; kk < 13; kk++) {
        float4 a = *reinterpret_cast<const float4*>(a1row + kk * 4);
        float av[4] = {a.x, a.y, a.z, a.w};
#pragma unroll
        for (int q = 0; q < 4; q++) {
            int k = kk * 4 + q;
            if (k >= FH) break;
            float v = av[q];
#pragma unroll
            for (int jj = 0; jj < FOUT / 4; jj++) {
                float4 w = *reinterpret_cast<const float4*>(&Ws[k * FOUT + jj * 4]);
                acc[jj * 4 + 0] += v * w.x;
                acc[jj * 4 + 1] += v * w.y;
                acc[jj * 4 + 2] += v * w.z;
                acc[jj * 4 + 3] += v * w.w;
            }
        }
    }
    // pack 40 floats -> 40 halves -> 5 uint4 stores
#pragma unroll
    for (int s = 0; s < 5; s++) {
        __half2 p0 = __floats2half2_rn(acc[s * 8 + 0], acc[s * 8 + 1]);
        __half2 p1 = __floats2half2_rn(acc[s * 8 + 2], acc[s * 8 + 3]);
        __half2 p2 = __floats2half2_rn(acc[s * 8 + 4], acc[s * 8 + 5]);
        __half2 p3 = __floats2half2_rn(acc[s * 8 + 6], acc[s * 8 + 7]);
        uint4 u;
        u.x = *reinterpret_cast<uint32_t*>(&p0);
        u.y = *reinterpret_cast<uint32_t*>(&p1);
        u.z = *reinterpret_cast<uint32_t*>(&p2);
        u.w = *reinterpret_cast<uint32_t*>(&p3);
        *reinterpret_cast<uint4*>(g_h2h + row * FOUT + s * 8) = u;
    }
}

// ---------------- agg2 + log_softmax fused (fp16 gather) -------------------
__global__ void agg2_ls_kernel(float* __restrict__ out) {
    int t = blockIdx.x * blockDim.x + threadIdx.x;
    int node = t >> 4;
    int ch = t & 15;
    bool valid = (node < NN);
    bool act = valid && (ch < 10);

    float4 acc = make_float4(0.f, 0.f, 0.f, 0.f);
    float4 acc2 = make_float4(0.f, 0.f, 0.f, 0.f);

    if (act) {
        int j = g_off[node];
        int end = g_off[node + 1];
        for (; j + 1 < end; j += 2) {
            int r0 = g_adj[j];
            int r1 = g_adj[j + 1];
            float d0 = g_dinv[r0];
            float d1 = g_dinv[r1];
            uint2 u0 = *reinterpret_cast<const uint2*>(g_h2h + r0 * FOUT + ch * 4);
            uint2 u1 = *reinterpret_cast<const uint2*>(g_h2h + r1 * FOUT + ch * 4);
            float2 a0 = __half22float2(*reinterpret_cast<__half2*>(&u0.x));
            float2 b0 = __half22float2(*reinterpret_cast<__half2*>(&u0.y));
            float2 a1 = __half22float2(*reinterpret_cast<__half2*>(&u1.x));
            float2 b1 = __half22float2(*reinterpret_cast<__half2*>(&u1.y));
            acc.x  += d0 * a0.x; acc.y  += d0 * a0.y; acc.z  += d0 * b0.x; acc.w  += d0 * b0.y;
            acc2.x += d1 * a1.x; acc2.y += d1 * a1.y; acc2.z += d1 * b1.x; acc2.w += d1 * b1.y;
        }
        if (j < end) {
            int r0 = g_adj[j];
            float d0 = g_dinv[r0];
            uint2 u0 = *reinterpret_cast<const uint2*>(g_h2h + r0 * FOUT + ch * 4);
            float2 a0 = __half22float2(*reinterpret_cast<__half2*>(&u0.x));
            float2 b0 = __half22float2(*reinterpret_cast<__half2*>(&u0.y));
            acc.x += d0 * a0.x; acc.y += d0 * a0.y; acc.z += d0 * b0.x; acc.w += d0 * b0.y;
        }
        float dc = g_dinv[node];
        acc.x = dc * (acc.x + acc2.x);
        acc.y = dc * (acc.y + acc2.y);
        acc.z = dc * (acc.z + acc2.z);
        acc.w = dc * (acc.w + acc2.w);
    }

    float m = act ? fmaxf(fmaxf(acc.x, acc.y), fmaxf(acc.z, acc.w)) : -INFINITY;
#pragma unroll
    for (int d = 8; d > 0; d >>= 1)
        m = fmaxf(m, __shfl_down_sync(0xffffffffu, m, d, 16));
    m = __shfl_sync(0xffffffffu, m, 0, 16);

    float s = act ? (expf(acc.x - m) + expf(acc.y - m) + expf(acc.z - m) + expf(acc.w - m)) : 0.f;
#pragma unroll
    for (int d = 8; d > 0; d >>= 1)
        s += __shfl_down_sync(0xffffffffu, s, d, 16);
    s = __shfl_sync(0xffffffffu, s, 0, 16);

    float l = m + logf(s);
    if (act) {
        *reinterpret_cast<float4*>(out + node * FOUT + ch * 4) =
            make_float4(acc.x - l, acc.y - l, acc.z - l, acc.w - l);
    }
}

// ---------------- launch (single stream) -----------------------------------
extern "C" void kernel_launch(void* const* d_in, const int* in_sizes, int n_in,
                              void* d_out, int out_size) {
    const float* x   = (const float*)d_in[0];
    const int*   ei  = (const int*)d_in[1];   // int32 (JAX x64 disabled)
    const float* W1  = (const float*)d_in[2];
    const float* b1  = (const float*)d_in[3];
    const float* W2  = (const float*)d_in[4];
    const float* b2  = (const float*)d_in[5];
    float*       out = (float*)d_out;

    const int T = 256;

    // CSR build
    ones_kernel<<<(NN + T - 1) / T, T>>>();
    prep_kernel<<<(EE / 4 + T - 1) / T, T>>>(ei);
    scanA_kernel<<<SCAN_NB, SCAN_BS>>>();
    scanB_kernel<<<1, 256>>>();
    scanC_kernel<<<SCAN_NB, SCAN_BS>>>();
    fill_kernel<<<(ET + T - 1) / T, T>>>(ei);

    // layer 1
    gemm1_tf32_kernel<<<(NN + 127) / 128, T>>>(x, W1, b1);
    agg1_kernel<<<(NN * 16 + T - 1) / T, T>>>();

    // layer 2
    gemm2_kernel<<<(NN + T - 1) / T, T>>>(W2, b2);
    agg2_ls_kernel<<<(NN * 16 + T - 1) / T, T>>>(out);
}